// round 8
// baseline (speedup 1.0000x reference)
#include <cuda_runtime.h>
#include <cstdint>
#include <float.h>
#include <limits.h>

#define CONF_THRESH 0.25f
#define CHUNK_ROWS  64
#define CHUNK_F     (CHUNK_ROWS * 80)           // 5120 floats
#define CHUNK_F4    (CHUNK_F / 4)               // 1280 float4 = 20 KB
#define NCHUNKS_MAX 2048
#define THREADS     256
#define WARPS       (THREADS / 32)
#define GRID        740                         // 148 SMs x 5 blocks (40KB smem)

// Scratch (__device__ globals; no cudaMalloc allowed).
__device__ float        g_chunksum[NCHUNKS_MAX];   // per-chunk sum, index = chunk id
__device__ int          g_blockmin[4096];
__device__ unsigned int g_work = 0;                // dynamic chunk counter (elected block resets)
__device__ unsigned int g_counter = 0;             // modulo exit ticket: no reset needed

__device__ __forceinline__ uint32_t smem_u32(const void* p) {
    uint32_t a;
    asm("{ .reg .u64 t; cvta.to.shared.u64 t, %1; cvt.u32.u64 %0, t; }"
        : "=r"(a) : "l"(p));
    return a;
}

__device__ __forceinline__ void stage_chunk(uint32_t sdst, const float4* gsrc) {
    #pragma unroll
    for (int k = 0; k < 5; k++) {
        const int idx = threadIdx.x + k * THREADS;
        asm volatile("cp.async.cg.shared.global [%0], [%1], 16;"
                     :: "r"(sdst + idx * 16), "l"(gsrc + idx) : "memory");
    }
}

__global__ void __launch_bounds__(THREADS)
fused_kernel(const float* __restrict__ post, float* __restrict__ out, int K) {
    __shared__ alignas(16) float tile[2][CHUNK_F];
    __shared__ int   sChunk[2];       // chunk id per stage, -1 = invalid
    __shared__ int   sDone;           // counter exhausted
    __shared__ int   sLast;
    __shared__ float sWs[WARPS];
    __shared__ int   sWm[WARPS];

    const int tid  = threadIdx.x;
    const int lane = tid & 31;
    const int wid  = tid >> 5;
    const int nchunks = (K + CHUNK_ROWS - 1) / CHUNK_ROWS;   // 2048

    const float4*  base = reinterpret_cast<const float4*>(post);
    const uint32_t sadr[2] = { smem_u32(tile[0]), smem_u32(tile[1]) };

    // ---- prologue: fetch + stage two chunks ----
    if (tid == 0) {
        sDone = 0;
        int c0 = (int)atomicAdd(&g_work, 1u);
        if (c0 >= nchunks) { c0 = -1; sDone = 1; }
        sChunk[0] = c0;
        int c1 = -1;
        if (!sDone) {
            c1 = (int)atomicAdd(&g_work, 1u);
            if (c1 >= nchunks) { c1 = -1; sDone = 1; }
        }
        sChunk[1] = c1;
    }
    __syncthreads();
    if (sChunk[0] >= 0) stage_chunk(sadr[0], base + (size_t)sChunk[0] * CHUNK_F4);
    asm volatile("cp.async.commit_group;" ::: "memory");
    if (sChunk[1] >= 0) stage_chunk(sadr[1], base + (size_t)sChunk[1] * CHUNK_F4);
    asm volatile("cp.async.commit_group;" ::: "memory");

    // ---- main loop ----
    const int sub = tid & 3;          // quarter of a row
    const int r0  = tid >> 2;         // 0..63
    int wmin = INT_MAX;               // per-block min (order-independent)
    int s = 0;

    for (;;) {
        asm volatile("cp.async.wait_group 1;" ::: "memory");
        __syncthreads();

        const int c = sChunk[s];
        float csum = 0.0f;            // this thread's contribution to chunk sum
        if (c >= 0) {
            const float4* rp =
                reinterpret_cast<const float4*>(tile[s] + r0 * 80) + sub * 5;
            float m = -FLT_MAX;
            #pragma unroll
            for (int i = 0; i < 5; i++) {
                float4 v = rp[i];
                m = fmaxf(m, fmaxf(fmaxf(v.x, v.y), fmaxf(v.z, v.w)));
            }
            m = fmaxf(m, __shfl_xor_sync(0xffffffffu, m, 1));
            m = fmaxf(m, __shfl_xor_sync(0xffffffffu, m, 2));
            const int grow = c * CHUNK_ROWS + r0;
            if (sub == 0 && grow < K) {
                csum = m;
                if (m < CONF_THRESH) wmin = min(wmin, grow);
            }
        }
        // block-reduce this chunk's sum (fixed order within chunk -> deterministic)
        #pragma unroll
        for (int o = 16; o > 0; o >>= 1)
            csum += __shfl_xor_sync(0xffffffffu, csum, o);
        if (lane == 0) sWs[wid] = csum;
        // fetch next chunk for this stage while reduce data settles
        if (tid == 0) {
            int cn = -1;
            if (!sDone) {
                cn = (int)atomicAdd(&g_work, 1u);
                if (cn >= nchunks) { cn = -1; sDone = 1; }
            }
            sChunk[s] = cn;
        }
        __syncthreads();              // covers: tile[s] reads done, sWs, sChunk[s]

        if (c >= 0 && tid < 32) {
            float bs = (lane < WARPS) ? sWs[lane] : 0.0f;
            #pragma unroll
            for (int o = 4; o > 0; o >>= 1)
                bs += __shfl_xor_sync(0xffffffffu, bs, o);
            if (lane == 0) g_chunksum[c] = bs;
        }

        const int cn = sChunk[s];
        if (cn >= 0) stage_chunk(sadr[s], base + (size_t)cn * CHUNK_F4);
        asm volatile("cp.async.commit_group;" ::: "memory");
        s ^= 1;
        if (sChunk[0] < 0 && sChunk[1] < 0) break;
    }
    asm volatile("cp.async.wait_group 0;" ::: "memory");

    // ---- per-block min reduce + exit ticket ----
    #pragma unroll
    for (int o = 16; o > 0; o >>= 1)
        wmin = min(wmin, __shfl_xor_sync(0xffffffffu, wmin, o));
    if (lane == 0) sWm[wid] = wmin;
    __syncthreads();
    if (tid < 32) {
        int mn = (lane < WARPS) ? sWm[lane] : INT_MAX;
        #pragma unroll
        for (int o = 4; o > 0; o >>= 1)
            mn = min(mn, __shfl_xor_sync(0xffffffffu, mn, o));
        if (lane == 0) {
            g_blockmin[blockIdx.x] = mn;
            __threadfence();
            unsigned int t = atomicAdd(&g_counter, 1u);
            sLast = ((t % gridDim.x) == gridDim.x - 1) ? 1 : 0;
        }
    }
    __syncthreads();
    if (!sLast) return;

    // ================= elected last block =================
    if (tid == 0) g_work = 0;         // reset for next graph replay (all fetches done)

    // fixed-order deterministic sum over chunks + grid-wide min
    float fsum = 0.0f;
    for (int i = tid; i < nchunks; i += THREADS)
        fsum += g_chunksum[i];
    int fmin = INT_MAX;
    for (int i = tid; i < gridDim.x; i += THREADS)
        fmin = min(fmin, g_blockmin[i]);
    #pragma unroll
    for (int o = 16; o > 0; o >>= 1) {
        fsum += __shfl_xor_sync(0xffffffffu, fsum, o);
        fmin  = min(fmin, __shfl_xor_sync(0xffffffffu, fmin, o));
    }
    __shared__ float fWs[WARPS];
    __shared__ int   fWm[WARPS];
    __shared__ int   sCut;
    if (lane == 0) { fWs[wid] = fsum; fWm[wid] = fmin; }
    __syncthreads();
    if (tid < 32) {
        float s2  = (lane < WARPS) ? fWs[lane] : 0.0f;
        int   mn2 = (lane < WARPS) ? fWm[lane] : INT_MAX;
        #pragma unroll
        for (int o = 4; o > 0; o >>= 1) {
            s2  += __shfl_xor_sync(0xffffffffu, s2, o);
            mn2  = min(mn2, __shfl_xor_sync(0xffffffffu, mn2, o));
        }
        if (lane == 0) {
            int cutoff = min(mn2, K);
            sCut = cutoff;
            if (cutoff >= K) out[0] = s2;   // common path
        }
    }
    __syncthreads();

    // ---- rare fixup (P ~ 0.25^80): recompute prefix [0, cutoff) from gmem ----
    const int cutoff = sCut;
    if (cutoff < K) {
        float fs = 0.0f;
        for (int r = tid; r < cutoff; r += THREADS) {
            const float4* rp = reinterpret_cast<const float4*>(post + (size_t)r * 80);
            float m = -FLT_MAX;
            #pragma unroll
            for (int i = 0; i < 20; i++) {
                float4 v = __ldg(rp + i);
                m = fmaxf(m, fmaxf(fmaxf(v.x, v.y), fmaxf(v.z, v.w)));
            }
            fs += m;
        }
        #pragma unroll
        for (int o = 16; o > 0; o >>= 1)
            fs += __shfl_xor_sync(0xffffffffu, fs, o);
        if (lane == 0) fWs[wid] = fs;
        __syncthreads();
        if (tid < 32) {
            float f2 = (lane < WARPS) ? fWs[lane] : 0.0f;
            #pragma unroll
            for (int o = 4; o > 0; o >>= 1)
                f2 += __shfl_xor_sync(0xffffffffu, f2, o);
            if (lane == 0) out[0] = f2;
        }
    }
}

extern "C" void kernel_launch(void* const* d_in, const int* in_sizes, int n_in,
                              void* d_out, int out_size) {
    const float* post = (const float*)d_in[0];
    float* out = (float*)d_out;

    const int n_rows = in_sizes[0] / 80;   // 262144
    const int K      = n_rows / 2;         // ratio = 0.5 -> 131072

    const int nchunks = (K + CHUNK_ROWS - 1) / CHUNK_ROWS;
    const int grid = GRID < nchunks ? GRID : nchunks;
    fused_kernel<<<grid, THREADS>>>(post, out, K);
}

// round 10
// speedup vs baseline: 1.0773x; 1.0773x over previous
#include <cuda_runtime.h>
#include <cstdint>
#include <float.h>
#include <limits.h>

#define CONF_THRESH   0.25f
#define ROWS_PER_TILE 128
#define TILE_FLOATS   (ROWS_PER_TILE * 80)      // 10240 floats = 2560 float4
#define TILE_BYTES    (TILE_FLOATS * 4)         // 40960 B
#define HALF_F4       1280                      // float4s per 64-row half
#define THREADS       256
#define WARPS         (THREADS / 32)
#define CONC          740                       // 148 SMs x 5 resident blocks

// Scratch (__device__ globals; no cudaMalloc allowed).
__device__ float        g_partials[4096];
__device__ int          g_blockmin[4096];
__device__ unsigned int g_counter = 0;          // modulo ticket: no reset needed

__device__ __forceinline__ uint32_t smem_u32(const void* p) {
    uint32_t a;
    asm("{ .reg .u64 t; cvta.to.shared.u64 t, %1; cvt.u32.u64 %0, t; }"
        : "=r"(a) : "l"(p));
    return a;
}

__global__ void __launch_bounds__(THREADS)
fused_kernel(const float* __restrict__ post, float* __restrict__ out, int K) {
    __shared__ alignas(16) float tile[TILE_FLOATS];
    __shared__ int   sLast;
    __shared__ float sWs[WARPS];
    __shared__ int   sWm[WARPS];

    const int tid  = threadIdx.x;
    const int lane = tid & 31;
    const int wid  = tid >> 5;

    // ---- stage own tile via cp.async.cg: 10 x 16B per thread, 2 groups ----
    const float4* gsrc = reinterpret_cast<const float4*>(post) +
                         (size_t)blockIdx.x * (TILE_FLOATS / 4);
    const uint32_t sbase = smem_u32(tile);

    #pragma unroll
    for (int k = 0; k < 5; k++) {               // half 0: rows 0..63
        const int idx = tid + k * THREADS;
        asm volatile("cp.async.cg.shared.global [%0], [%1], 16;"
                     :: "r"(sbase + idx * 16), "l"(gsrc + idx) : "memory");
    }
    asm volatile("cp.async.commit_group;" ::: "memory");
    #pragma unroll
    for (int k = 0; k < 5; k++) {               // half 1: rows 64..127
        const int idx = HALF_F4 + tid + k * THREADS;
        asm volatile("cp.async.cg.shared.global [%0], [%1], 16;"
                     :: "r"(sbase + idx * 16), "l"(gsrc + idx) : "memory");
    }
    asm volatile("cp.async.commit_group;" ::: "memory");

    // ---- cross-wave L2 prefetch: pull the wave-2 successor's tile into L2
    //      while this (wave-1) block streams its own tile from DRAM.
    //      Fire-and-forget; no completion dependency anywhere. ----
    {
        const int pf = blockIdx.x + CONC;
        if (pf < (int)gridDim.x) {
            const char* p = (const char*)(post) + (size_t)pf * TILE_BYTES;
            #pragma unroll
            for (int k = 0; k < 2; k++) {       // 320 lines of 128B, 256 threads
                const int line = tid + k * THREADS;
                if (line < TILE_BYTES / 128)
                    asm volatile("prefetch.global.L2 [%0];"
                                 :: "l"(p + (size_t)line * 128));
            }
        }
    }

    // ---- row maxes from smem: 4 threads per row, 5 LDS.128 each ----
    const int sub = tid & 3;          // quarter within row
    const int r0  = tid >> 2;         // 0..63
    float wsum = 0.0f;
    int   wmin = INT_MAX;

    #pragma unroll
    for (int j = 0; j < 2; j++) {
        if (j == 0) asm volatile("cp.async.wait_group 1;" ::: "memory");
        else        asm volatile("cp.async.wait_group 0;" ::: "memory");
        __syncthreads();              // make staged half visible block-wide

        const int row  = j * 64 + r0;
        const int grow = blockIdx.x * ROWS_PER_TILE + row;
        const float4* rp = reinterpret_cast<const float4*>(tile + row * 80) + sub * 5;
        float m = -FLT_MAX;
        #pragma unroll
        for (int i = 0; i < 5; i++) {
            float4 v = rp[i];
            m = fmaxf(m, fmaxf(fmaxf(v.x, v.y), fmaxf(v.z, v.w)));
        }
        m = fmaxf(m, __shfl_xor_sync(0xffffffffu, m, 1));
        m = fmaxf(m, __shfl_xor_sync(0xffffffffu, m, 2));
        if (sub == 0 && grow < K) {
            wsum += m;
            if (m < CONF_THRESH) wmin = min(wmin, grow);
        }
    }

    // ---- warp reduce ----
    #pragma unroll
    for (int o = 16; o > 0; o >>= 1) {
        wsum += __shfl_xor_sync(0xffffffffu, wsum, o);
        wmin  = min(wmin, __shfl_xor_sync(0xffffffffu, wmin, o));
    }
    if (lane == 0) { sWs[wid] = wsum; sWm[wid] = wmin; }
    __syncthreads();

    // ---- block reduce + ticket ----
    if (tid < 32) {
        float s  = (lane < WARPS) ? sWs[lane] : 0.0f;
        int   mn = (lane < WARPS) ? sWm[lane] : INT_MAX;
        #pragma unroll
        for (int o = 4; o > 0; o >>= 1) {
            s  += __shfl_xor_sync(0xffffffffu, s, o);
            mn  = min(mn, __shfl_xor_sync(0xffffffffu, mn, o));
        }
        if (lane == 0) {
            g_partials[blockIdx.x] = s;
            g_blockmin[blockIdx.x] = mn;
            __threadfence();
            unsigned int t = atomicAdd(&g_counter, 1u);
            sLast = ((t % gridDim.x) == gridDim.x - 1) ? 1 : 0;
        }
    }
    __syncthreads();
    if (!sLast) return;

    // ================= elected last block: final reduce =================
    float s  = 0.0f;
    int   mn = INT_MAX;
    for (int i = tid; i < gridDim.x; i += THREADS) {
        s  += g_partials[i];
        mn  = min(mn, g_blockmin[i]);
    }
    #pragma unroll
    for (int o = 16; o > 0; o >>= 1) {
        s  += __shfl_xor_sync(0xffffffffu, s, o);
        mn  = min(mn, __shfl_xor_sync(0xffffffffu, mn, o));
    }
    __shared__ float fWs[WARPS];
    __shared__ int   fWm[WARPS];
    __shared__ int   sCut;
    if (lane == 0) { fWs[wid] = s; fWm[wid] = mn; }
    __syncthreads();
    if (tid < 32) {
        float s2  = (lane < WARPS) ? fWs[lane] : 0.0f;
        int   mn2 = (lane < WARPS) ? fWm[lane] : INT_MAX;
        #pragma unroll
        for (int o = 4; o > 0; o >>= 1) {
            s2  += __shfl_xor_sync(0xffffffffu, s2, o);
            mn2  = min(mn2, __shfl_xor_sync(0xffffffffu, mn2, o));
        }
        if (lane == 0) {
            int cutoff = min(mn2, K);
            sCut = cutoff;
            if (cutoff >= K) out[0] = s2;   // common path
        }
    }
    __syncthreads();

    // ---- rare fixup (P ~ 0.25^80): recompute prefix [0, cutoff) from gmem ----
    const int cutoff = sCut;
    if (cutoff < K) {
        float fs = 0.0f;
        for (int r = tid; r < cutoff; r += THREADS) {
            const float4* rp = reinterpret_cast<const float4*>(post + (size_t)r * 80);
            float m = -FLT_MAX;
            #pragma unroll
            for (int i = 0; i < 20; i++) {
                float4 v = __ldg(rp + i);
                m = fmaxf(m, fmaxf(fmaxf(v.x, v.y), fmaxf(v.z, v.w)));
            }
            fs += m;
        }
        #pragma unroll
        for (int o = 16; o > 0; o >>= 1)
            fs += __shfl_xor_sync(0xffffffffu, fs, o);
        if (lane == 0) fWs[wid] = fs;
        __syncthreads();
        if (tid < 32) {
            float f2 = (lane < WARPS) ? fWs[lane] : 0.0f;
            #pragma unroll
            for (int o = 4; o > 0; o >>= 1)
                f2 += __shfl_xor_sync(0xffffffffu, f2, o);
            if (lane == 0) out[0] = f2;
        }
    }
}

extern "C" void kernel_launch(void* const* d_in, const int* in_sizes, int n_in,
                              void* d_out, int out_size) {
    const float* post = (const float*)d_in[0];
    float* out = (float*)d_out;

    const int n_rows = in_sizes[0] / 80;   // 262144
    const int K      = n_rows / 2;         // ratio = 0.5 -> 131072

    const int blocks = (K + ROWS_PER_TILE - 1) / ROWS_PER_TILE;  // 1024
    fused_kernel<<<blocks, THREADS>>>(post, out, K);
}

// round 13
// speedup vs baseline: 1.0885x; 1.0104x over previous
#include <cuda_runtime.h>
#include <cstdint>
#include <float.h>
#include <limits.h>

#define CONF_THRESH   0.25f
#define ROWS_PER_TILE 64
#define TILE_FLOATS   (ROWS_PER_TILE * 80)      // 5120 floats = 1280 float4 = 20 KB
#define TILE_F4       (TILE_FLOATS / 4)
#define THREADS       128
#define WARPS         (THREADS / 32)            // 4

// Scratch (__device__ globals; no cudaMalloc allowed).
__device__ float        g_partials[4096];
__device__ int          g_blockmin[4096];
__device__ unsigned int g_counter = 0;          // modulo ticket: no reset needed

__device__ __forceinline__ uint32_t smem_u32(const void* p) {
    uint32_t a;
    asm("{ .reg .u64 t; cvta.to.shared.u64 t, %1; cvt.u32.u64 %0, t; }"
        : "=r"(a) : "l"(p));
    return a;
}

__global__ void __launch_bounds__(THREADS)
fused_kernel(const float* __restrict__ post, float* __restrict__ out, int K) {
    __shared__ alignas(16) float tile[TILE_FLOATS];
    __shared__ int   sLast;
    __shared__ float sWs[WARPS];
    __shared__ int   sWm[WARPS];

    const int tid  = threadIdx.x;
    const int lane = tid & 31;
    const int wid  = tid >> 5;

    // ---- stage 20KB tile via cp.async.cg: 10 x 16B per thread, 1 group ----
    const float4* gsrc = reinterpret_cast<const float4*>(post) +
                         (size_t)blockIdx.x * TILE_F4;
    const uint32_t sbase = smem_u32(tile);

    #pragma unroll
    for (int k = 0; k < 10; k++) {
        const int idx = tid + k * THREADS;
        asm volatile("cp.async.cg.shared.global [%0], [%1], 16;"
                     :: "r"(sbase + idx * 16), "l"(gsrc + idx) : "memory");
    }
    asm volatile("cp.async.commit_group;" ::: "memory");
    asm volatile("cp.async.wait_group 0;" ::: "memory");
    __syncthreads();                  // tile visible block-wide

    // ---- row maxes from smem: 4 threads per row, 5 LDS.128 each, 2 rows/thread ----
    const int sub = tid & 3;          // quarter within row
    const int r0  = tid >> 2;         // 0..31

    float wsum = 0.0f;
    int   wmin = INT_MAX;

    #pragma unroll
    for (int j = 0; j < 2; j++) {
        const int row  = r0 + j * 32;                 // 0..63
        const int grow = blockIdx.x * ROWS_PER_TILE + row;
        const float4* rp = reinterpret_cast<const float4*>(tile + row * 80) + sub * 5;
        float m = -FLT_MAX;
        #pragma unroll
        for (int i = 0; i < 5; i++) {
            float4 v = rp[i];
            m = fmaxf(m, fmaxf(fmaxf(v.x, v.y), fmaxf(v.z, v.w)));
        }
        m = fmaxf(m, __shfl_xor_sync(0xffffffffu, m, 1));
        m = fmaxf(m, __shfl_xor_sync(0xffffffffu, m, 2));
        if (sub == 0 && grow < K) {
            wsum += m;
            if (m < CONF_THRESH) wmin = min(wmin, grow);
        }
    }

    // ---- warp reduce ----
    #pragma unroll
    for (int o = 16; o > 0; o >>= 1) {
        wsum += __shfl_xor_sync(0xffffffffu, wsum, o);
        wmin  = min(wmin, __shfl_xor_sync(0xffffffffu, wmin, o));
    }
    if (lane == 0) { sWs[wid] = wsum; sWm[wid] = wmin; }
    __syncthreads();

    // ---- block reduce + ticket ----
    if (tid < 32) {
        float s  = (lane < WARPS) ? sWs[lane] : 0.0f;
        int   mn = (lane < WARPS) ? sWm[lane] : INT_MAX;
        #pragma unroll
        for (int o = 2; o > 0; o >>= 1) {
            s  += __shfl_xor_sync(0xffffffffu, s, o);
            mn  = min(mn, __shfl_xor_sync(0xffffffffu, mn, o));
        }
        if (lane == 0) {
            g_partials[blockIdx.x] = s;
            g_blockmin[blockIdx.x] = mn;
            __threadfence();
            unsigned int t = atomicAdd(&g_counter, 1u);
            sLast = ((t % gridDim.x) == gridDim.x - 1) ? 1 : 0;
        }
    }
    __syncthreads();
    if (!sLast) return;

    // ================= elected last block: final reduce =================
    float s  = 0.0f;
    int   mn = INT_MAX;
    for (int i = tid; i < (int)gridDim.x; i += THREADS) {
        s  += g_partials[i];
        mn  = min(mn, g_blockmin[i]);
    }
    #pragma unroll
    for (int o = 16; o > 0; o >>= 1) {
        s  += __shfl_xor_sync(0xffffffffu, s, o);
        mn  = min(mn, __shfl_xor_sync(0xffffffffu, mn, o));
    }
    __shared__ float fWs[WARPS];
    __shared__ int   fWm[WARPS];
    __shared__ int   sCut;
    if (lane == 0) { fWs[wid] = s; fWm[wid] = mn; }
    __syncthreads();
    if (tid < 32) {
        float s2  = (lane < WARPS) ? fWs[lane] : 0.0f;
        int   mn2 = (lane < WARPS) ? fWm[lane] : INT_MAX;
        #pragma unroll
        for (int o = 2; o > 0; o >>= 1) {
            s2  += __shfl_xor_sync(0xffffffffu, s2, o);
            mn2  = min(mn2, __shfl_xor_sync(0xffffffffu, mn2, o));
        }
        if (lane == 0) {
            int cutoff = min(mn2, K);
            sCut = cutoff;
            if (cutoff >= K) out[0] = s2;   // common path
        }
    }
    __syncthreads();

    // ---- rare fixup (P ~ 0.25^80): recompute prefix [0, cutoff) from gmem ----
    const int cutoff = sCut;
    if (cutoff < K) {
        float fs = 0.0f;
        for (int r = tid; r < cutoff; r += THREADS) {
            const float4* rr = reinterpret_cast<const float4*>(post + (size_t)r * 80);
            float mm = -FLT_MAX;
            #pragma unroll 5
            for (int i = 0; i < 20; i++) {
                float4 v = __ldg(rr + i);
                mm = fmaxf(mm, fmaxf(fmaxf(v.x, v.y), fmaxf(v.z, v.w)));
            }
            fs += mm;
        }
        #pragma unroll
        for (int o = 16; o > 0; o >>= 1)
            fs += __shfl_xor_sync(0xffffffffu, fs, o);
        if (lane == 0) fWs[wid] = fs;
        __syncthreads();
        if (tid < 32) {
            float f2 = (lane < WARPS) ? fWs[lane] : 0.0f;
            #pragma unroll
            for (int o = 2; o > 0; o >>= 1)
                f2 += __shfl_xor_sync(0xffffffffu, f2, o);
            if (lane == 0) out[0] = f2;
        }
    }
}

extern "C" void kernel_launch(void* const* d_in, const int* in_sizes, int n_in,
                              void* d_out, int out_size) {
    const float* post = (const float*)d_in[0];
    float* out = (float*)d_out;

    const int n_rows = in_sizes[0] / 80;   // 262144
    const int K      = n_rows / 2;         // ratio = 0.5 -> 131072

    const int blocks = (K + ROWS_PER_TILE - 1) / ROWS_PER_TILE;  // 2048
    fused_kernel<<<blocks, THREADS>>>(post, out, K);
}